// round 15
// baseline (speedup 1.0000x reference)
#include <cuda_runtime.h>
#include <cuda_fp16.h>
#include <math_constants.h>
#include <cstdint>

// Problem constants
#define NN      50000
#define EE      800000
#define IN_DIM  256
#define HD      256      // NHEAD * OUT_DIM
#define OUT_DIM 64
#define NHEAD   4
#define SLOPE   0.2f
#define BN_EPS  1e-5f

// ---------------- scratch (static device arrays; no cudaMalloc) ------------
__device__ __half g_hsrcH[NN * HD];   // h_src in fp16 (halves edge-gather bytes)
__device__ float  g_hdst[NN * HD];    // h_dst; overwritten in-place with rst
__device__ float  g_z[NN * OUT_DIM];  // fc output
__device__ int    g_deg[NN];
__device__ int    g_cnt[NN];
__device__ int    g_rowptr[NN + 1];
__device__ int    g_ecol[EE];         // src node id per CSR slot
__device__ int    g_bsum[256], g_boff[256];
__device__ float  g_sum[OUT_DIM], g_sumsq[OUT_DIM];
__device__ float  g_mu[OUT_DIM], g_istd[OUT_DIM];

// fp16 transposed weights [n][k], K-major (K=256)
__device__ __half g_wst[HD * IN_DIM];      // W_src^T
__device__ __half g_wdt[HD * IN_DIM];      // W_dst^T
__device__ __half g_wft[OUT_DIM * HD];     // fc_W^T

// ---------------- PTX helpers ----------------------------------------------
__device__ __forceinline__ uint32_t smem_u32(const void* p) {
    uint32_t a;
    asm("{ .reg .u64 t; cvta.to.shared.u64 t, %1; cvt.u32.u64 %0, t; }" : "=r"(a) : "l"(p));
    return a;
}
__device__ __forceinline__ void ldm_x4(uint32_t* r, uint32_t addr) {
    asm volatile("ldmatrix.sync.aligned.m8n8.x4.shared.b16 {%0,%1,%2,%3}, [%4];"
        : "=r"(r[0]), "=r"(r[1]), "=r"(r[2]), "=r"(r[3]) : "r"(addr));
}
__device__ __forceinline__ void mma16816h(float* d, const uint32_t* a, const uint32_t* b) {
    asm volatile(
        "mma.sync.aligned.m16n8k16.row.col.f32.f16.f16.f32 "
        "{%0,%1,%2,%3}, {%4,%5,%6,%7}, {%8,%9}, {%0,%1,%2,%3};"
        : "+f"(d[0]), "+f"(d[1]), "+f"(d[2]), "+f"(d[3])
        : "r"(a[0]), "r"(a[1]), "r"(a[2]), "r"(a[3]), "r"(b[0]), "r"(b[1]));
}
__device__ __forceinline__ void cp16(uint32_t dst, const void* src) {
    asm volatile("cp.async.ca.shared.global [%0], [%1], 16;" :: "r"(dst), "l"(src));
}
__device__ __forceinline__ void cp_commit() {
    asm volatile("cp.async.commit_group;" ::: "memory");
}
__device__ __forceinline__ void cp_wait0() {
    asm volatile("cp.async.wait_group 0;" ::: "memory");
}
// 8 fp32 -> 8 fp16 packed in one uint4
__device__ __forceinline__ void conv8h(const float4& a, const float4& b, uint4& h) {
    __half2 h0 = __floats2half2_rn(a.x, a.y);
    __half2 h1 = __floats2half2_rn(a.z, a.w);
    __half2 h2 = __floats2half2_rn(b.x, b.y);
    __half2 h3 = __floats2half2_rn(b.z, b.w);
    h = make_uint4(*reinterpret_cast<uint32_t*>(&h0), *reinterpret_cast<uint32_t*>(&h1),
                   *reinterpret_cast<uint32_t*>(&h2), *reinterpret_cast<uint32_t*>(&h3));
}

// ---------------- init / CSR build -----------------------------------------
__global__ void k_init() {
    int i = blockIdx.x * blockDim.x + threadIdx.x;
    int stride = gridDim.x * blockDim.x;
    for (int j = i; j < NN; j += stride) { g_deg[j] = 0; g_cnt[j] = 0; }
    if (i < OUT_DIM) { g_sum[i] = 0.f; g_sumsq[i] = 0.f; }
    if (i == 0) g_rowptr[0] = 0;
}

__global__ void k_count(const int* __restrict__ dst) {
    int i = blockIdx.x * blockDim.x + threadIdx.x;
    if (i < EE) atomicAdd(&g_deg[dst[i]], 1);
}

// merged transpose + fp16 round of all three weight matrices
__global__ void k_wtrans_all(const float* __restrict__ Ws,
                             const float* __restrict__ Wd,
                             const float* __restrict__ Wf)
{
    int i = blockIdx.x * blockDim.x + threadIdx.x;
    if (i < 65536) {
        int n = i >> 8, k = i & 255;
        g_wst[i] = __float2half_rn(Ws[k * HD + n]);
    } else if (i < 131072) {
        int j = i - 65536;
        int n = j >> 8, k = j & 255;
        g_wdt[j] = __float2half_rn(Wd[k * HD + n]);
    } else if (i < 147456) {
        int j = i - 131072;
        int n = j >> 8, k = j & 255;
        g_wft[j] = __float2half_rn(Wf[k * OUT_DIM + n]);
    }
}

// ---- multi-block scan ----
#define SCAN_B 196   // ceil(50000 / 256)
__global__ void k_scan1() {
    __shared__ int wsum[8];
    int tid = threadIdx.x, lane = tid & 31, wid = tid >> 5;
    int i = blockIdx.x * 256 + tid;
    int v = (i < NN) ? g_deg[i] : 0;
    int s = v;
#pragma unroll
    for (int off = 1; off < 32; off <<= 1) {
        int t = __shfl_up_sync(0xffffffffu, s, off);
        if (lane >= off) s += t;
    }
    if (lane == 31) wsum[wid] = s;
    __syncthreads();
    if (wid == 0 && lane < 8) {
        int w = wsum[lane];
#pragma unroll
        for (int off = 1; off < 8; off <<= 1) {
            int t = __shfl_up_sync(0xffu, w, off);
            if (lane >= off) w += t;
        }
        wsum[lane] = w;
    }
    __syncthreads();
    int incl = s + (wid ? wsum[wid - 1] : 0);
    if (i < NN) g_rowptr[i + 1] = incl;
    if (tid == 255) g_bsum[blockIdx.x] = incl;
}

__global__ void k_scan2() {
    __shared__ int wsum[8];
    int tid = threadIdx.x, lane = tid & 31, wid = tid >> 5;
    int v = (tid < SCAN_B) ? g_bsum[tid] : 0;
    int s = v;
#pragma unroll
    for (int off = 1; off < 32; off <<= 1) {
        int t = __shfl_up_sync(0xffffffffu, s, off);
        if (lane >= off) s += t;
    }
    if (lane == 31) wsum[wid] = s;
    __syncthreads();
    if (wid == 0 && lane < 8) {
        int w = wsum[lane];
#pragma unroll
        for (int off = 1; off < 8; off <<= 1) {
            int t = __shfl_up_sync(0xffu, w, off);
            if (lane >= off) w += t;
        }
        wsum[lane] = w;
    }
    __syncthreads();
    int incl = s + (wid ? wsum[wid - 1] : 0);
    g_boff[tid] = incl - v;
}

__global__ void k_scan3() {
    int i = blockIdx.x * 256 + threadIdx.x;
    if (i < NN) g_rowptr[i + 1] += g_boff[blockIdx.x];
}

__global__ void k_scatter(const int* __restrict__ src, const int* __restrict__ dst) {
    int i = blockIdx.x * blockDim.x + threadIdx.x;
    if (i < EE) {
        int v = dst[i];
        int pos = g_rowptr[v] + atomicAdd(&g_cnt[v], 1);
        g_ecol[pos] = src[i];
    }
}

// ---------------- pure fp16 GEMM: C[M,Nn] = A @ Bt^T + bias ----------------
// A fp32 row-major (K=256), rounded to fp16 in-kernel while staging.
// Bt pre-transposed fp16 ([n][k] K-major). Single product per fragment.
// CTA tile 128 x NT, 8 warps (4m x 2n), warp tile 32 x NT/2, m16n8k16.f16.
// HALF0: z==0 writes fp16 C. BNSTAT: fused BatchNorm column statistics.
template <int NT, bool HALF0, bool BNSTAT>
__global__ __launch_bounds__(256, 2)
void k_mma_gemm(
    const float* __restrict__ A,
    const __half* __restrict__ Bt0, const __half* __restrict__ Bt1,
    const float* __restrict__ bias0, const float* __restrict__ bias1,
    void* __restrict__ C0v, void* __restrict__ C1v,
    int M, int Nn)
{
    constexpr int A_BYTES = 128 * 80;            // 128 rows x (32 fp16 + pad)
    constexpr int B_BYTES = NT * 80;
    constexpr int STAGE   = A_BYTES + B_BYTES;
    constexpr int NG      = NT / 32;
    constexpr int B_IT    = NT * 4 / 256;

    extern __shared__ char smem[];
    const uint32_t sb = smem_u32(smem);
    const int tid  = threadIdx.x;
    const int lane = tid & 31;
    const int w    = tid >> 5;
    const int wr   = w & 3;
    const int wc   = w >> 2;

    const bool z0 = (blockIdx.z == 0);
    const __half* Bt   = z0 ? Bt0 : Bt1;
    const float*  bias = z0 ? bias0 : bias1;

    const int rowBase = blockIdx.y * 128;
    const int colBase = blockIdx.x * NT;

    float acc[2][2 * NG][4];
#pragma unroll
    for (int a = 0; a < 2; a++)
#pragma unroll
        for (int b = 0; b < 2 * NG; b++)
#pragma unroll
            for (int c = 0; c < 4; c++) acc[a][b][c] = 0.f;

    const int ar0 = tid >> 2, ap0 = tid & 3;
    const int ar1 = (tid + 256) >> 2, ap1 = ap0;
    int grow0 = rowBase + ar0; if (grow0 >= M) grow0 = M - 1;
    int grow1 = rowBase + ar1; if (grow1 >= M) grow1 = M - 1;

    float4 rA[4];

    auto loadA = [&](int ck) {
        const float* p0 = &A[(size_t)grow0 * 256 + ck * 32 + ap0 * 8];
        const float* p1 = &A[(size_t)grow1 * 256 + ck * 32 + ap1 * 8];
        rA[0] = *(const float4*)p0; rA[1] = *(const float4*)(p0 + 4);
        rA[2] = *(const float4*)p1; rA[3] = *(const float4*)(p1 + 4);
    };
    auto storeA = [&](int stage) {
        uint32_t st = (uint32_t)stage * STAGE;
        uint4 h;
        conv8h(rA[0], rA[1], h);
        *(uint4*)(smem + st + ar0 * 80 + ap0 * 16) = h;
        conv8h(rA[2], rA[3], h);
        *(uint4*)(smem + st + ar1 * 80 + ap1 * 16) = h;
    };
    auto loadB = [&](int ck, int stage) {
        uint32_t st = (uint32_t)stage * STAGE + A_BYTES;
#pragma unroll
        for (int i = 0; i < B_IT; i++) {
            int idx = tid + i * 256;
            int r = idx >> 2, p = idx & 3;
            uint32_t off = st + r * 80 + p * 16;
            size_t g = (size_t)(colBase + r) * 256 + ck * 32 + p * 8;
            cp16(sb + off, &Bt[g]);
        }
        cp_commit();
    };

    loadA(0);
    loadB(0, 0);
    storeA(0);
    cp_wait0();
    __syncthreads();

    const int lr = (lane & 7) + ((lane >> 3) & 1) * 8;
    const int lk = (lane >> 4) * 8;

    for (int ck = 0; ck < 8; ck++) {
        if (ck < 7) { loadA(ck + 1); loadB(ck + 1, (ck + 1) & 1); }

        const uint32_t stg = (uint32_t)(ck & 1) * STAGE;
        const uint32_t sA = sb + stg;
        const uint32_t sB = sA + A_BYTES;

#pragma unroll
        for (int k16 = 0; k16 < 32; k16 += 16) {
            uint32_t a[2][4];
#pragma unroll
            for (int mt = 0; mt < 2; mt++) {
                uint32_t off = (uint32_t)(wr * 32 + mt * 16 + lr) * 80 + (k16 + lk) * 2;
                ldm_x4(a[mt], sA + off);
            }
#pragma unroll
            for (int ng = 0; ng < NG; ng++) {
                uint32_t off = (uint32_t)(wc * (NT / 2) + ng * 16 + lr) * 80 + (k16 + lk) * 2;
                uint32_t t[4];
                ldm_x4(t, sB + off);
                uint32_t b0[2] = {t[0], t[2]}, b1[2] = {t[1], t[3]};
#pragma unroll
                for (int mt = 0; mt < 2; mt++) {
                    mma16816h(acc[mt][ng * 2],     a[mt], b0);
                    mma16816h(acc[mt][ng * 2 + 1], a[mt], b1);
                }
            }
        }

        if (ck < 7) { storeA((ck + 1) & 1); cp_wait0(); }
        __syncthreads();
    }

    // ---- epilogue (+ optional fused BatchNorm statistics) ----
    float colS[2 * NG][2], colQ[2 * NG][2];
    if (BNSTAT) {
#pragma unroll
        for (int nt = 0; nt < 2 * NG; nt++) {
            colS[nt][0] = colS[nt][1] = 0.f;
            colQ[nt][0] = colQ[nt][1] = 0.f;
        }
    }

#pragma unroll
    for (int mt = 0; mt < 2; mt++) {
#pragma unroll
        for (int nt = 0; nt < 2 * NG; nt++) {
            int gr = rowBase + wr * 32 + mt * 16 + (lane >> 2);
            int gc = colBase + wc * (NT / 2) + nt * 8 + (lane & 3) * 2;
            float b0 = bias[gc], b1 = bias[gc + 1];
            float v0 = acc[mt][nt][0] + b0, v1 = acc[mt][nt][1] + b1;
            float v2 = acc[mt][nt][2] + b0, v3 = acc[mt][nt][3] + b1;
            if (HALF0 && z0) {
                __half* Ch = (__half*)C0v;
                if (gr < M)
                    *(__half2*)&Ch[(size_t)gr * Nn + gc] = __floats2half2_rn(v0, v1);
                if (gr + 8 < M)
                    *(__half2*)&Ch[(size_t)(gr + 8) * Nn + gc] = __floats2half2_rn(v2, v3);
            } else {
                float* Cf = (float*)(z0 ? C0v : C1v);
                if (gr < M)
                    *(float2*)&Cf[(size_t)gr * Nn + gc] = make_float2(v0, v1);
                if (gr + 8 < M)
                    *(float2*)&Cf[(size_t)(gr + 8) * Nn + gc] = make_float2(v2, v3);
            }
            if (BNSTAT) {
                if (gr < M)     { colS[nt][0] += v0; colQ[nt][0] += v0 * v0;
                                  colS[nt][1] += v1; colQ[nt][1] += v1 * v1; }
                if (gr + 8 < M) { colS[nt][0] += v2; colQ[nt][0] += v2 * v2;
                                  colS[nt][1] += v3; colQ[nt][1] += v3 * v3; }
            }
        }
    }

    if (BNSTAT) {
#pragma unroll
        for (int nt = 0; nt < 2 * NG; nt++)
#pragma unroll
            for (int c = 0; c < 2; c++) {
#pragma unroll
                for (int msk = 4; msk <= 16; msk <<= 1) {
                    colS[nt][c] += __shfl_xor_sync(0xffffffffu, colS[nt][c], msk);
                    colQ[nt][c] += __shfl_xor_sync(0xffffffffu, colQ[nt][c], msk);
                }
            }
        __syncthreads();                   // mainloop SMEM fully retired
        float* bn = (float*)smem;          // [0:64) sum, [64:128) sumsq
        if (tid < 128) bn[tid] = 0.f;
        __syncthreads();
        if ((lane >> 2) == 0) {            // lanes 0..3 of each warp hold totals
#pragma unroll
            for (int nt = 0; nt < 2 * NG; nt++)
#pragma unroll
                for (int c = 0; c < 2; c++) {
                    int col = wc * (NT / 2) + nt * 8 + (lane & 3) * 2 + c;
                    atomicAdd(&bn[col], colS[nt][c]);
                    atomicAdd(&bn[64 + col], colQ[nt][c]);
                }
        }
        __syncthreads();
        if (tid < 64) {
            atomicAdd(&g_sum[tid],   bn[tid]);
            atomicAdd(&g_sumsq[tid], bn[64 + tid]);
        }
    }
}

// ---------------- edge aggregation: warp per dst node, online softmax ------
// Latency-pipelined: coalesced batch index loads (lane l reads ecol[b+l],
// broadcast via shfl) + 4-deep data-prefetch ring -> 4 outstanding gathers.
__global__ __launch_bounds__(256) void k_edge_agg(
    const float* __restrict__ attn, const float* __restrict__ out_bias)
{
    int warp = (blockIdx.x * blockDim.x + threadIdx.x) >> 5;
    int lane = threadIdx.x & 31;
    if (warp >= NN) return;
    int v = warp;
    int base = lane * 8;

    float hd[8], at[8];
    {
        float4 d0 = *(const float4*)&g_hdst[v * HD + base];
        float4 d1 = *(const float4*)&g_hdst[v * HD + base + 4];
        hd[0]=d0.x; hd[1]=d0.y; hd[2]=d0.z; hd[3]=d0.w;
        hd[4]=d1.x; hd[5]=d1.y; hd[6]=d1.z; hd[7]=d1.w;
        float4 t0 = *(const float4*)&attn[base];
        float4 t1 = *(const float4*)&attn[base + 4];
        at[0]=t0.x; at[1]=t0.y; at[2]=t0.z; at[3]=t0.w;
        at[4]=t1.x; at[5]=t1.y; at[6]=t1.z; at[7]=t1.w;
    }

    float m = -CUDART_INF_F;
    float s = 0.f;
    float acc[8];
#pragma unroll
    for (int i = 0; i < 8; i++) acc[i] = 0.f;

    const int start = g_rowptr[v];
    const int end   = g_rowptr[v + 1];

    for (int b = start; b < end; b += 32) {
        const int cnt = min(32, end - b);
        // coalesced: lane l fetches edge index b+l
        int bidx = (b + lane < end) ? g_ecol[b + lane] : 0;

        uint4 ring[4];
#pragma unroll
        for (int p = 0; p < 4; p++) {
            if (p < cnt) {
                int up = __shfl_sync(0xffffffffu, bidx, p);
                ring[p] = *(const uint4*)&g_hsrcH[(size_t)up * HD + base];
            }
        }

        for (int k = 0; k < cnt; k++) {
            uint4 cur = ring[k & 3];
            int kp = k + 4;
            if (kp < cnt) {
                int up = __shfl_sync(0xffffffffu, bidx, kp);
                ring[k & 3] = *(const uint4*)&g_hsrcH[(size_t)up * HD + base];
            }

            const __half2* ph = (const __half2*)&cur;
            float2 f0 = __half22float2(ph[0]);
            float2 f1 = __half22float2(ph[1]);
            float2 f2 = __half22float2(ph[2]);
            float2 f3 = __half22float2(ph[3]);
            float hs[8] = {f0.x, f0.y, f1.x, f1.y, f2.x, f2.y, f3.x, f3.y};

            float e = 0.f;
#pragma unroll
            for (int i = 0; i < 8; i++) {
                float x = hs[i] + hd[i];
                x = (x >= 0.f) ? x : SLOPE * x;
                e = fmaf(at[i], x, e);
            }
            e += __shfl_xor_sync(0xffffffffu, e, 1);
            e += __shfl_xor_sync(0xffffffffu, e, 2);
            e += __shfl_xor_sync(0xffffffffu, e, 4);
            float nm = fmaxf(m, e);
            float sc = __expf(m - nm);
            float p  = __expf(e - nm);
            s = s * sc + p;
#pragma unroll
            for (int i = 0; i < 8; i++)
                acc[i] = fmaf(acc[i], sc, p * hs[i]);
            m = nm;
        }
    }

    float inv = (s > 0.f) ? (1.0f / s) : 0.f;
    float4 ob0 = *(const float4*)&out_bias[base];
    float4 ob1 = *(const float4*)&out_bias[base + 4];
    float4 o0, o1;
    o0.x = acc[0] * inv + ob0.x; o0.y = acc[1] * inv + ob0.y;
    o0.z = acc[2] * inv + ob0.z; o0.w = acc[3] * inv + ob0.w;
    o1.x = acc[4] * inv + ob1.x; o1.y = acc[5] * inv + ob1.y;
    o1.z = acc[6] * inv + ob1.z; o1.w = acc[7] * inv + ob1.w;
    *(float4*)&g_hdst[v * HD + base]     = o0;   // rst (fc GEMM input)
    *(float4*)&g_hdst[v * HD + base + 4] = o1;
}

// ---------------- BatchNorm tail -------------------------------------------
__global__ void k_bn_finalize() {
    int c = threadIdx.x;
    if (c < OUT_DIM) {
        float mu = g_sum[c] / (float)NN;
        float var = g_sumsq[c] / (float)NN - mu * mu;
        g_mu[c] = mu;
        g_istd[c] = rsqrtf(var + BN_EPS);
    }
}

__global__ void k_bn_apply(const float* __restrict__ gamma,
                           const float* __restrict__ beta,
                           float* __restrict__ out)
{
    int i = blockIdx.x * blockDim.x + threadIdx.x;
    int stride = gridDim.x * blockDim.x;
    for (int j = i; j < NN * OUT_DIM; j += stride) {
        int c = j & 63;
        float x = (g_z[j] - g_mu[c]) * g_istd[c] * gamma[c] + beta[c];
        out[j] = (x >= 0.f) ? x : SLOPE * x;
    }
}

// ---------------- launch ----------------------------------------------------
extern "C" void kernel_launch(void* const* d_in, const int* in_sizes, int n_in,
                              void* d_out, int out_size)
{
    const float* feat    = (const float*)d_in[0];
    const int*   src     = (const int*)  d_in[1];
    const int*   dst     = (const int*)  d_in[2];
    const float* W_src   = (const float*)d_in[3];
    const float* b_src   = (const float*)d_in[4];
    const float* W_dst   = (const float*)d_in[5];
    const float* b_dst   = (const float*)d_in[6];
    const float* attn    = (const float*)d_in[7];
    const float* outbias = (const float*)d_in[8];
    const float* fc_W    = (const float*)d_in[9];
    const float* fc_b    = (const float*)d_in[10];
    const float* gamma   = (const float*)d_in[11];
    const float* beta    = (const float*)d_in[12];
    float* out = (float*)d_out;

    float *p_hdst, *p_z;
    __half* p_hsrcH;
    cudaGetSymbolAddress((void**)&p_hsrcH, g_hsrcH);
    cudaGetSymbolAddress((void**)&p_hdst, g_hdst);
    cudaGetSymbolAddress((void**)&p_z,    g_z);
    __half *p_wst, *p_wdt, *p_wft;
    cudaGetSymbolAddress((void**)&p_wst, g_wst);
    cudaGetSymbolAddress((void**)&p_wdt, g_wdt);
    cudaGetSymbolAddress((void**)&p_wft, g_wft);

    // stage = A + B, double-buffered
    const int SMEM_FRONT = 2 * (128 * 80 + 128 * 80);  // 40960
    const int SMEM_FC    = 2 * (128 * 80 + 64 * 80);   // 30720
    cudaFuncSetAttribute((const void*)k_mma_gemm<128, true, false>,
                         cudaFuncAttributeMaxDynamicSharedMemorySize, SMEM_FRONT);
    cudaFuncSetAttribute((const void*)k_mma_gemm<64, false, true>,
                         cudaFuncAttributeMaxDynamicSharedMemorySize, SMEM_FC);

    // Fork a side stream: CSR build (s0) overlaps weight prep + front GEMM (sB).
    cudaStream_t sB;
    cudaStreamCreateWithFlags(&sB, cudaStreamNonBlocking);
    cudaEvent_t evRoot, evB;
    cudaEventCreateWithFlags(&evRoot, cudaEventDisableTiming);
    cudaEventCreateWithFlags(&evB, cudaEventDisableTiming);

    cudaEventRecord(evRoot, 0);
    cudaStreamWaitEvent(sB, evRoot, 0);

    k_wtrans_all<<<(147456 + 255) / 256, 256, 0, sB>>>(W_src, W_dst, fc_W);  // 0
    k_init<<<256, 256>>>();                                                   // 1
    k_count<<<(EE + 255) / 256, 256>>>(dst);                                  // 2
    k_scan1<<<SCAN_B, 256>>>();                                               // 3
    k_scan2<<<1, 256>>>();                                                    // 4
    {                                                                         // 5: front GEMM
        dim3 grid(HD / 128, (NN + 127) / 128, 2);
        k_mma_gemm<128, true, false><<<grid, 256, SMEM_FRONT, sB>>>(
            feat, p_wst, p_wdt, b_src, b_dst,
            (void*)p_hsrcH, (void*)p_hdst, NN, HD);
    }
    cudaEventRecord(evB, sB);
    k_scan3<<<SCAN_B, 256>>>();                                               // 6
    k_scatter<<<(EE + 255) / 256, 256>>>(src, dst);                           // 7

    cudaStreamWaitEvent(0, evB, 0);

    k_edge_agg<<<(NN * 32 + 255) / 256, 256>>>(attn, outbias);                // 8

    {                                                                         // 9: fc GEMM + fused BN stats
        dim3 grid(1, (NN + 127) / 128, 1);
        k_mma_gemm<64, false, true><<<grid, 256, SMEM_FC>>>(
            p_hdst, p_wft, p_wft, fc_b, fc_b,
            (void*)p_z, (void*)p_z, NN, OUT_DIM);
    }

    k_bn_finalize<<<1, 64>>>();                                               // 10
    k_bn_apply<<<512, 256>>>(gamma, beta, out);                               // 11
}

// round 16
// speedup vs baseline: 1.0461x; 1.0461x over previous
#include <cuda_runtime.h>
#include <cuda_fp16.h>
#include <math_constants.h>
#include <cstdint>

// Problem constants
#define NN      50000
#define EE      800000
#define IN_DIM  256
#define HD      256      // NHEAD * OUT_DIM
#define OUT_DIM 64
#define NHEAD   4
#define SLOPE   0.2f
#define BN_EPS  1e-5f

// ---------------- scratch (static device arrays; no cudaMalloc) ------------
__device__ __half g_hsrcH[NN * HD];   // h_src in fp16 (halves edge-gather bytes)
__device__ float  g_hdst[NN * HD];    // h_dst; overwritten in-place with rst
__device__ float  g_z[NN * OUT_DIM];  // fc output
__device__ int    g_deg[NN];
__device__ int    g_cnt[NN];
__device__ int    g_rowptr[NN + 1];
__device__ int    g_ecol[EE];         // src node id per CSR slot
__device__ int    g_bsum[256], g_boff[256];
__device__ float  g_sum[OUT_DIM], g_sumsq[OUT_DIM];
__device__ float  g_mu[OUT_DIM], g_istd[OUT_DIM];

// fp16 transposed weights [n][k], K-major (K=256)
__device__ __half g_wst[HD * IN_DIM];      // W_src^T
__device__ __half g_wdt[HD * IN_DIM];      // W_dst^T
__device__ __half g_wft[OUT_DIM * HD];     // fc_W^T

// ---------------- PTX helpers ----------------------------------------------
__device__ __forceinline__ uint32_t smem_u32(const void* p) {
    uint32_t a;
    asm("{ .reg .u64 t; cvta.to.shared.u64 t, %1; cvt.u32.u64 %0, t; }" : "=r"(a) : "l"(p));
    return a;
}
__device__ __forceinline__ void ldm_x4(uint32_t* r, uint32_t addr) {
    asm volatile("ldmatrix.sync.aligned.m8n8.x4.shared.b16 {%0,%1,%2,%3}, [%4];"
        : "=r"(r[0]), "=r"(r[1]), "=r"(r[2]), "=r"(r[3]) : "r"(addr));
}
__device__ __forceinline__ void mma16816h(float* d, const uint32_t* a, const uint32_t* b) {
    asm volatile(
        "mma.sync.aligned.m16n8k16.row.col.f32.f16.f16.f32 "
        "{%0,%1,%2,%3}, {%4,%5,%6,%7}, {%8,%9}, {%0,%1,%2,%3};"
        : "+f"(d[0]), "+f"(d[1]), "+f"(d[2]), "+f"(d[3])
        : "r"(a[0]), "r"(a[1]), "r"(a[2]), "r"(a[3]), "r"(b[0]), "r"(b[1]));
}
__device__ __forceinline__ void cp16(uint32_t dst, const void* src) {
    asm volatile("cp.async.ca.shared.global [%0], [%1], 16;" :: "r"(dst), "l"(src));
}
__device__ __forceinline__ void cp_commit() {
    asm volatile("cp.async.commit_group;" ::: "memory");
}
__device__ __forceinline__ void cp_wait0() {
    asm volatile("cp.async.wait_group 0;" ::: "memory");
}
// 8 fp32 -> 8 fp16 packed in one uint4
__device__ __forceinline__ void conv8h(const float4& a, const float4& b, uint4& h) {
    __half2 h0 = __floats2half2_rn(a.x, a.y);
    __half2 h1 = __floats2half2_rn(a.z, a.w);
    __half2 h2 = __floats2half2_rn(b.x, b.y);
    __half2 h3 = __floats2half2_rn(b.z, b.w);
    h = make_uint4(*reinterpret_cast<uint32_t*>(&h0), *reinterpret_cast<uint32_t*>(&h1),
                   *reinterpret_cast<uint32_t*>(&h2), *reinterpret_cast<uint32_t*>(&h3));
}

// ---------------- init / CSR build -----------------------------------------
__global__ void k_init() {
    int i = blockIdx.x * blockDim.x + threadIdx.x;
    int stride = gridDim.x * blockDim.x;
    for (int j = i; j < NN; j += stride) { g_deg[j] = 0; g_cnt[j] = 0; }
    if (i < OUT_DIM) { g_sum[i] = 0.f; g_sumsq[i] = 0.f; }
    if (i == 0) g_rowptr[0] = 0;
}

__global__ void k_count(const int* __restrict__ dst) {
    int i = blockIdx.x * blockDim.x + threadIdx.x;
    if (i < EE) atomicAdd(&g_deg[dst[i]], 1);
}

// merged transpose + fp16 round of all three weight matrices
__global__ void k_wtrans_all(const float* __restrict__ Ws,
                             const float* __restrict__ Wd,
                             const float* __restrict__ Wf)
{
    int i = blockIdx.x * blockDim.x + threadIdx.x;
    if (i < 65536) {
        int n = i >> 8, k = i & 255;
        g_wst[i] = __float2half_rn(Ws[k * HD + n]);
    } else if (i < 131072) {
        int j = i - 65536;
        int n = j >> 8, k = j & 255;
        g_wdt[j] = __float2half_rn(Wd[k * HD + n]);
    } else if (i < 147456) {
        int j = i - 131072;
        int n = j >> 8, k = j & 255;
        g_wft[j] = __float2half_rn(Wf[k * OUT_DIM + n]);
    }
}

// ---- multi-block scan ----
#define SCAN_B 196   // ceil(50000 / 256)
__global__ void k_scan1() {
    __shared__ int wsum[8];
    int tid = threadIdx.x, lane = tid & 31, wid = tid >> 5;
    int i = blockIdx.x * 256 + tid;
    int v = (i < NN) ? g_deg[i] : 0;
    int s = v;
#pragma unroll
    for (int off = 1; off < 32; off <<= 1) {
        int t = __shfl_up_sync(0xffffffffu, s, off);
        if (lane >= off) s += t;
    }
    if (lane == 31) wsum[wid] = s;
    __syncthreads();
    if (wid == 0 && lane < 8) {
        int w = wsum[lane];
#pragma unroll
        for (int off = 1; off < 8; off <<= 1) {
            int t = __shfl_up_sync(0xffu, w, off);
            if (lane >= off) w += t;
        }
        wsum[lane] = w;
    }
    __syncthreads();
    int incl = s + (wid ? wsum[wid - 1] : 0);
    if (i < NN) g_rowptr[i + 1] = incl;
    if (tid == 255) g_bsum[blockIdx.x] = incl;
}

__global__ void k_scan2() {
    __shared__ int wsum[8];
    int tid = threadIdx.x, lane = tid & 31, wid = tid >> 5;
    int v = (tid < SCAN_B) ? g_bsum[tid] : 0;
    int s = v;
#pragma unroll
    for (int off = 1; off < 32; off <<= 1) {
        int t = __shfl_up_sync(0xffffffffu, s, off);
        if (lane >= off) s += t;
    }
    if (lane == 31) wsum[wid] = s;
    __syncthreads();
    if (wid == 0 && lane < 8) {
        int w = wsum[lane];
#pragma unroll
        for (int off = 1; off < 8; off <<= 1) {
            int t = __shfl_up_sync(0xffu, w, off);
            if (lane >= off) w += t;
        }
        wsum[lane] = w;
    }
    __syncthreads();
    int incl = s + (wid ? wsum[wid - 1] : 0);
    g_boff[tid] = incl - v;
}

__global__ void k_scan3() {
    int i = blockIdx.x * 256 + threadIdx.x;
    if (i < NN) g_rowptr[i + 1] += g_boff[blockIdx.x];
}

__global__ void k_scatter(const int* __restrict__ src, const int* __restrict__ dst) {
    int i = blockIdx.x * blockDim.x + threadIdx.x;
    if (i < EE) {
        int v = dst[i];
        int pos = g_rowptr[v] + atomicAdd(&g_cnt[v], 1);
        g_ecol[pos] = src[i];
    }
}

// ---------------- pure fp16 GEMM: C[M,Nn] = A @ Bt^T + bias ----------------
// A fp32 row-major (K=256), rounded to fp16 in-kernel while staging.
// Bt pre-transposed fp16 ([n][k] K-major). Single product per fragment.
// CTA tile 128 x NT, 8 warps (4m x 2n), warp tile 32 x NT/2, m16n8k16.f16.
// HALF0: z==0 writes fp16 C. BNSTAT: fused BatchNorm column statistics.
template <int NT, bool HALF0, bool BNSTAT>
__global__ __launch_bounds__(256, 2)
void k_mma_gemm(
    const float* __restrict__ A,
    const __half* __restrict__ Bt0, const __half* __restrict__ Bt1,
    const float* __restrict__ bias0, const float* __restrict__ bias1,
    void* __restrict__ C0v, void* __restrict__ C1v,
    int M, int Nn)
{
    constexpr int A_BYTES = 128 * 80;            // 128 rows x (32 fp16 + pad)
    constexpr int B_BYTES = NT * 80;
    constexpr int STAGE   = A_BYTES + B_BYTES;
    constexpr int NG      = NT / 32;
    constexpr int B_IT    = NT * 4 / 256;

    extern __shared__ char smem[];
    const uint32_t sb = smem_u32(smem);
    const int tid  = threadIdx.x;
    const int lane = tid & 31;
    const int w    = tid >> 5;
    const int wr   = w & 3;
    const int wc   = w >> 2;

    const bool z0 = (blockIdx.z == 0);
    const __half* Bt   = z0 ? Bt0 : Bt1;
    const float*  bias = z0 ? bias0 : bias1;

    const int rowBase = blockIdx.y * 128;
    const int colBase = blockIdx.x * NT;

    float acc[2][2 * NG][4];
#pragma unroll
    for (int a = 0; a < 2; a++)
#pragma unroll
        for (int b = 0; b < 2 * NG; b++)
#pragma unroll
            for (int c = 0; c < 4; c++) acc[a][b][c] = 0.f;

    const int ar0 = tid >> 2, ap0 = tid & 3;
    const int ar1 = (tid + 256) >> 2, ap1 = ap0;
    int grow0 = rowBase + ar0; if (grow0 >= M) grow0 = M - 1;
    int grow1 = rowBase + ar1; if (grow1 >= M) grow1 = M - 1;

    float4 rA[4];

    auto loadA = [&](int ck) {
        const float* p0 = &A[(size_t)grow0 * 256 + ck * 32 + ap0 * 8];
        const float* p1 = &A[(size_t)grow1 * 256 + ck * 32 + ap1 * 8];
        rA[0] = *(const float4*)p0; rA[1] = *(const float4*)(p0 + 4);
        rA[2] = *(const float4*)p1; rA[3] = *(const float4*)(p1 + 4);
    };
    auto storeA = [&](int stage) {
        uint32_t st = (uint32_t)stage * STAGE;
        uint4 h;
        conv8h(rA[0], rA[1], h);
        *(uint4*)(smem + st + ar0 * 80 + ap0 * 16) = h;
        conv8h(rA[2], rA[3], h);
        *(uint4*)(smem + st + ar1 * 80 + ap1 * 16) = h;
    };
    auto loadB = [&](int ck, int stage) {
        uint32_t st = (uint32_t)stage * STAGE + A_BYTES;
#pragma unroll
        for (int i = 0; i < B_IT; i++) {
            int idx = tid + i * 256;
            int r = idx >> 2, p = idx & 3;
            uint32_t off = st + r * 80 + p * 16;
            size_t g = (size_t)(colBase + r) * 256 + ck * 32 + p * 8;
            cp16(sb + off, &Bt[g]);
        }
        cp_commit();
    };

    loadA(0);
    loadB(0, 0);
    storeA(0);
    cp_wait0();
    __syncthreads();

    const int lr = (lane & 7) + ((lane >> 3) & 1) * 8;
    const int lk = (lane >> 4) * 8;

    for (int ck = 0; ck < 8; ck++) {
        if (ck < 7) { loadA(ck + 1); loadB(ck + 1, (ck + 1) & 1); }

        const uint32_t stg = (uint32_t)(ck & 1) * STAGE;
        const uint32_t sA = sb + stg;
        const uint32_t sB = sA + A_BYTES;

#pragma unroll
        for (int k16 = 0; k16 < 32; k16 += 16) {
            uint32_t a[2][4];
#pragma unroll
            for (int mt = 0; mt < 2; mt++) {
                uint32_t off = (uint32_t)(wr * 32 + mt * 16 + lr) * 80 + (k16 + lk) * 2;
                ldm_x4(a[mt], sA + off);
            }
#pragma unroll
            for (int ng = 0; ng < NG; ng++) {
                uint32_t off = (uint32_t)(wc * (NT / 2) + ng * 16 + lr) * 80 + (k16 + lk) * 2;
                uint32_t t[4];
                ldm_x4(t, sB + off);
                uint32_t b0[2] = {t[0], t[2]}, b1[2] = {t[1], t[3]};
#pragma unroll
                for (int mt = 0; mt < 2; mt++) {
                    mma16816h(acc[mt][ng * 2],     a[mt], b0);
                    mma16816h(acc[mt][ng * 2 + 1], a[mt], b1);
                }
            }
        }

        if (ck < 7) { storeA((ck + 1) & 1); cp_wait0(); }
        __syncthreads();
    }

    // ---- epilogue (+ optional fused BatchNorm statistics) ----
    float colS[2 * NG][2], colQ[2 * NG][2];
    if (BNSTAT) {
#pragma unroll
        for (int nt = 0; nt < 2 * NG; nt++) {
            colS[nt][0] = colS[nt][1] = 0.f;
            colQ[nt][0] = colQ[nt][1] = 0.f;
        }
    }

#pragma unroll
    for (int mt = 0; mt < 2; mt++) {
#pragma unroll
        for (int nt = 0; nt < 2 * NG; nt++) {
            int gr = rowBase + wr * 32 + mt * 16 + (lane >> 2);
            int gc = colBase + wc * (NT / 2) + nt * 8 + (lane & 3) * 2;
            float b0 = bias[gc], b1 = bias[gc + 1];
            float v0 = acc[mt][nt][0] + b0, v1 = acc[mt][nt][1] + b1;
            float v2 = acc[mt][nt][2] + b0, v3 = acc[mt][nt][3] + b1;
            if (HALF0 && z0) {
                __half* Ch = (__half*)C0v;
                if (gr < M)
                    *(__half2*)&Ch[(size_t)gr * Nn + gc] = __floats2half2_rn(v0, v1);
                if (gr + 8 < M)
                    *(__half2*)&Ch[(size_t)(gr + 8) * Nn + gc] = __floats2half2_rn(v2, v3);
            } else {
                float* Cf = (float*)(z0 ? C0v : C1v);
                if (gr < M)
                    *(float2*)&Cf[(size_t)gr * Nn + gc] = make_float2(v0, v1);
                if (gr + 8 < M)
                    *(float2*)&Cf[(size_t)(gr + 8) * Nn + gc] = make_float2(v2, v3);
            }
            if (BNSTAT) {
                if (gr < M)     { colS[nt][0] += v0; colQ[nt][0] += v0 * v0;
                                  colS[nt][1] += v1; colQ[nt][1] += v1 * v1; }
                if (gr + 8 < M) { colS[nt][0] += v2; colQ[nt][0] += v2 * v2;
                                  colS[nt][1] += v3; colQ[nt][1] += v3 * v3; }
            }
        }
    }

    if (BNSTAT) {
#pragma unroll
        for (int nt = 0; nt < 2 * NG; nt++)
#pragma unroll
            for (int c = 0; c < 2; c++) {
#pragma unroll
                for (int msk = 4; msk <= 16; msk <<= 1) {
                    colS[nt][c] += __shfl_xor_sync(0xffffffffu, colS[nt][c], msk);
                    colQ[nt][c] += __shfl_xor_sync(0xffffffffu, colQ[nt][c], msk);
                }
            }
        __syncthreads();                   // mainloop SMEM fully retired
        float* bn = (float*)smem;          // [0:64) sum, [64:128) sumsq
        if (tid < 128) bn[tid] = 0.f;
        __syncthreads();
        if ((lane >> 2) == 0) {            // lanes 0..3 of each warp hold totals
#pragma unroll
            for (int nt = 0; nt < 2 * NG; nt++)
#pragma unroll
                for (int c = 0; c < 2; c++) {
                    int col = wc * (NT / 2) + nt * 8 + (lane & 3) * 2 + c;
                    atomicAdd(&bn[col], colS[nt][c]);
                    atomicAdd(&bn[64 + col], colQ[nt][c]);
                }
        }
        __syncthreads();
        if (tid < 64) {
            atomicAdd(&g_sum[tid],   bn[tid]);
            atomicAdd(&g_sumsq[tid], bn[64 + tid]);
        }
    }
}

// ---------------- edge aggregation: warp per dst node, online softmax ------
// Latency-pipelined with STATIC registers: coalesced index loads (lane l
// reads ecol[b+l], broadcast via shfl) + explicit 4-register prefetch ring,
// main loop unrolled by 4 so every ring slot is a named register.
struct EdgeState {
    float m, s;
    float acc[8];
};

__device__ __forceinline__ void edge_step(
    const uint4& cur, const float* hd, const float* at,
    float& m, float& s, float* acc)
{
    const __half2* ph = (const __half2*)&cur;
    float2 f0 = __half22float2(ph[0]);
    float2 f1 = __half22float2(ph[1]);
    float2 f2 = __half22float2(ph[2]);
    float2 f3 = __half22float2(ph[3]);
    float hs[8] = {f0.x, f0.y, f1.x, f1.y, f2.x, f2.y, f3.x, f3.y};

    float e = 0.f;
#pragma unroll
    for (int i = 0; i < 8; i++) {
        float x = hs[i] + hd[i];
        x = (x >= 0.f) ? x : SLOPE * x;
        e = fmaf(at[i], x, e);
    }
    e += __shfl_xor_sync(0xffffffffu, e, 1);
    e += __shfl_xor_sync(0xffffffffu, e, 2);
    e += __shfl_xor_sync(0xffffffffu, e, 4);
    float nm = fmaxf(m, e);
    float sc = __expf(m - nm);
    float p  = __expf(e - nm);
    s = s * sc + p;
#pragma unroll
    for (int i = 0; i < 8; i++)
        acc[i] = fmaf(acc[i], sc, p * hs[i]);
    m = nm;
}

__global__ __launch_bounds__(256) void k_edge_agg(
    const float* __restrict__ attn, const float* __restrict__ out_bias)
{
    int warp = (blockIdx.x * blockDim.x + threadIdx.x) >> 5;
    int lane = threadIdx.x & 31;
    if (warp >= NN) return;
    int v = warp;
    int base = lane * 8;

    float hd[8], at[8];
    {
        float4 d0 = *(const float4*)&g_hdst[v * HD + base];
        float4 d1 = *(const float4*)&g_hdst[v * HD + base + 4];
        hd[0]=d0.x; hd[1]=d0.y; hd[2]=d0.z; hd[3]=d0.w;
        hd[4]=d1.x; hd[5]=d1.y; hd[6]=d1.z; hd[7]=d1.w;
        float4 t0 = *(const float4*)&attn[base];
        float4 t1 = *(const float4*)&attn[base + 4];
        at[0]=t0.x; at[1]=t0.y; at[2]=t0.z; at[3]=t0.w;
        at[4]=t1.x; at[5]=t1.y; at[6]=t1.z; at[7]=t1.w;
    }

    float m = -CUDART_INF_F;
    float s = 0.f;
    float acc[8];
#pragma unroll
    for (int i = 0; i < 8; i++) acc[i] = 0.f;

    const int start = g_rowptr[v];
    const int end   = g_rowptr[v + 1];

    for (int b = start; b < end; b += 32) {
        const int cnt = min(32, end - b);             // warp-uniform
        int bidx = (b + lane < end) ? g_ecol[b + lane] : 0;   // coalesced

        // prologue: fill 4 named registers
        uint4 r0, r1, r2, r3;
        {
            int u0 = __shfl_sync(0xffffffffu, bidx, 0);
            r0 = *(const uint4*)&g_hsrcH[(size_t)u0 * HD + base];
        }
        if (cnt > 1) { int u = __shfl_sync(0xffffffffu, bidx, 1);
                       r1 = *(const uint4*)&g_hsrcH[(size_t)u * HD + base]; }
        if (cnt > 2) { int u = __shfl_sync(0xffffffffu, bidx, 2);
                       r2 = *(const uint4*)&g_hsrcH[(size_t)u * HD + base]; }
        if (cnt > 3) { int u = __shfl_sync(0xffffffffu, bidx, 3);
                       r3 = *(const uint4*)&g_hsrcH[(size_t)u * HD + base]; }

        int k = 0;
        for (; k + 4 <= cnt; k += 4) {
            edge_step(r0, hd, at, m, s, acc);
            if (k + 4 < cnt) { int u = __shfl_sync(0xffffffffu, bidx, k + 4);
                               r0 = *(const uint4*)&g_hsrcH[(size_t)u * HD + base]; }
            edge_step(r1, hd, at, m, s, acc);
            if (k + 5 < cnt) { int u = __shfl_sync(0xffffffffu, bidx, k + 5);
                               r1 = *(const uint4*)&g_hsrcH[(size_t)u * HD + base]; }
            edge_step(r2, hd, at, m, s, acc);
            if (k + 6 < cnt) { int u = __shfl_sync(0xffffffffu, bidx, k + 6);
                               r2 = *(const uint4*)&g_hsrcH[(size_t)u * HD + base]; }
            edge_step(r3, hd, at, m, s, acc);
            if (k + 7 < cnt) { int u = __shfl_sync(0xffffffffu, bidx, k + 7);
                               r3 = *(const uint4*)&g_hsrcH[(size_t)u * HD + base]; }
        }
        // tail (<=3 remaining edges live in r0..r2)
        int rem = cnt - k;
        if (rem > 0) edge_step(r0, hd, at, m, s, acc);
        if (rem > 1) edge_step(r1, hd, at, m, s, acc);
        if (rem > 2) edge_step(r2, hd, at, m, s, acc);
    }

    float inv = (s > 0.f) ? (1.0f / s) : 0.f;
    float4 ob0 = *(const float4*)&out_bias[base];
    float4 ob1 = *(const float4*)&out_bias[base + 4];
    float4 o0, o1;
    o0.x = acc[0] * inv + ob0.x; o0.y = acc[1] * inv + ob0.y;
    o0.z = acc[2] * inv + ob0.z; o0.w = acc[3] * inv + ob0.w;
    o1.x = acc[4] * inv + ob1.x; o1.y = acc[5] * inv + ob1.y;
    o1.z = acc[6] * inv + ob1.z; o1.w = acc[7] * inv + ob1.w;
    *(float4*)&g_hdst[v * HD + base]     = o0;   // rst (fc GEMM input)
    *(float4*)&g_hdst[v * HD + base + 4] = o1;
}

// ---------------- BatchNorm tail -------------------------------------------
__global__ void k_bn_finalize() {
    int c = threadIdx.x;
    if (c < OUT_DIM) {
        float mu = g_sum[c] / (float)NN;
        float var = g_sumsq[c] / (float)NN - mu * mu;
        g_mu[c] = mu;
        g_istd[c] = rsqrtf(var + BN_EPS);
    }
}

__global__ void k_bn_apply(const float* __restrict__ gamma,
                           const float* __restrict__ beta,
                           float* __restrict__ out)
{
    int i = blockIdx.x * blockDim.x + threadIdx.x;
    int stride = gridDim.x * blockDim.x;
    for (int j = i; j < NN * OUT_DIM; j += stride) {
        int c = j & 63;
        float x = (g_z[j] - g_mu[c]) * g_istd[c] * gamma[c] + beta[c];
        out[j] = (x >= 0.f) ? x : SLOPE * x;
    }
}

// ---------------- launch ----------------------------------------------------
extern "C" void kernel_launch(void* const* d_in, const int* in_sizes, int n_in,
                              void* d_out, int out_size)
{
    const float* feat    = (const float*)d_in[0];
    const int*   src     = (const int*)  d_in[1];
    const int*   dst     = (const int*)  d_in[2];
    const float* W_src   = (const float*)d_in[3];
    const float* b_src   = (const float*)d_in[4];
    const float* W_dst   = (const float*)d_in[5];
    const float* b_dst   = (const float*)d_in[6];
    const float* attn    = (const float*)d_in[7];
    const float* outbias = (const float*)d_in[8];
    const float* fc_W    = (const float*)d_in[9];
    const float* fc_b    = (const float*)d_in[10];
    const float* gamma   = (const float*)d_in[11];
    const float* beta    = (const float*)d_in[12];
    float* out = (float*)d_out;

    float *p_hdst, *p_z;
    __half* p_hsrcH;
    cudaGetSymbolAddress((void**)&p_hsrcH, g_hsrcH);
    cudaGetSymbolAddress((void**)&p_hdst, g_hdst);
    cudaGetSymbolAddress((void**)&p_z,    g_z);
    __half *p_wst, *p_wdt, *p_wft;
    cudaGetSymbolAddress((void**)&p_wst, g_wst);
    cudaGetSymbolAddress((void**)&p_wdt, g_wdt);
    cudaGetSymbolAddress((void**)&p_wft, g_wft);

    // stage = A + B, double-buffered
    const int SMEM_FRONT = 2 * (128 * 80 + 128 * 80);  // 40960
    const int SMEM_FC    = 2 * (128 * 80 + 64 * 80);   // 30720
    cudaFuncSetAttribute((const void*)k_mma_gemm<128, true, false>,
                         cudaFuncAttributeMaxDynamicSharedMemorySize, SMEM_FRONT);
    cudaFuncSetAttribute((const void*)k_mma_gemm<64, false, true>,
                         cudaFuncAttributeMaxDynamicSharedMemorySize, SMEM_FC);

    // Fork a side stream: CSR build (s0) overlaps weight prep + front GEMM (sB).
    cudaStream_t sB;
    cudaStreamCreateWithFlags(&sB, cudaStreamNonBlocking);
    cudaEvent_t evRoot, evB;
    cudaEventCreateWithFlags(&evRoot, cudaEventDisableTiming);
    cudaEventCreateWithFlags(&evB, cudaEventDisableTiming);

    cudaEventRecord(evRoot, 0);
    cudaStreamWaitEvent(sB, evRoot, 0);

    k_wtrans_all<<<(147456 + 255) / 256, 256, 0, sB>>>(W_src, W_dst, fc_W);  // 0
    k_init<<<256, 256>>>();                                                   // 1
    k_count<<<(EE + 255) / 256, 256>>>(dst);                                  // 2
    k_scan1<<<SCAN_B, 256>>>();                                               // 3
    k_scan2<<<1, 256>>>();                                                    // 4
    {                                                                         // 5: front GEMM
        dim3 grid(HD / 128, (NN + 127) / 128, 2);
        k_mma_gemm<128, true, false><<<grid, 256, SMEM_FRONT, sB>>>(
            feat, p_wst, p_wdt, b_src, b_dst,
            (void*)p_hsrcH, (void*)p_hdst, NN, HD);
    }
    cudaEventRecord(evB, sB);
    k_scan3<<<SCAN_B, 256>>>();                                               // 6
    k_scatter<<<(EE + 255) / 256, 256>>>(src, dst);                           // 7

    cudaStreamWaitEvent(0, evB, 0);

    k_edge_agg<<<(NN * 32 + 255) / 256, 256>>>(attn, outbias);                // 8

    {                                                                         // 9: fc GEMM + fused BN stats
        dim3 grid(1, (NN + 127) / 128, 1);
        k_mma_gemm<64, false, true><<<grid, 256, SMEM_FC>>>(
            p_hdst, p_wft, p_wft, fc_b, fc_b,
            (void*)p_z, (void*)p_z, NN, OUT_DIM);
    }

    k_bn_finalize<<<1, 64>>>();                                               // 10
    k_bn_apply<<<512, 256>>>(gamma, beta, out);                               // 11
}

// round 17
// speedup vs baseline: 1.0756x; 1.0282x over previous
#include <cuda_runtime.h>
#include <cuda_fp16.h>
#include <math_constants.h>
#include <cstdint>

// Problem constants
#define NN      50000
#define EE      800000
#define IN_DIM  256
#define HD      256      // NHEAD * OUT_DIM
#define OUT_DIM 64
#define NHEAD   4
#define SLOPE   0.2f
#define BN_EPS  1e-5f

// ---------------- scratch (static device arrays; no cudaMalloc) ------------
__device__ __half g_hsrcH[NN * HD];   // h_src in fp16 (halves edge-gather bytes)
__device__ float  g_hdst[NN * HD];    // h_dst; overwritten in-place with rst
__device__ float  g_z[NN * OUT_DIM];  // fc output
__device__ int    g_deg[NN];
__device__ int    g_cnt[NN];
__device__ int    g_rowptr[NN + 1];
__device__ int    g_ecol[EE];         // src node id per CSR slot
__device__ int    g_bsum[256], g_boff[256];
__device__ float  g_sum[OUT_DIM], g_sumsq[OUT_DIM];

// fp16 transposed weights [n][k], K-major (K=256)
__device__ __half g_wst[HD * IN_DIM];      // W_src^T
__device__ __half g_wdt[HD * IN_DIM];      // W_dst^T
__device__ __half g_wft[OUT_DIM * HD];     // fc_W^T

// ---------------- PTX helpers ----------------------------------------------
__device__ __forceinline__ uint32_t smem_u32(const void* p) {
    uint32_t a;
    asm("{ .reg .u64 t; cvta.to.shared.u64 t, %1; cvt.u32.u64 %0, t; }" : "=r"(a) : "l"(p));
    return a;
}
__device__ __forceinline__ void ldm_x4(uint32_t* r, uint32_t addr) {
    asm volatile("ldmatrix.sync.aligned.m8n8.x4.shared.b16 {%0,%1,%2,%3}, [%4];"
        : "=r"(r[0]), "=r"(r[1]), "=r"(r[2]), "=r"(r[3]) : "r"(addr));
}
__device__ __forceinline__ void mma16816h(float* d, const uint32_t* a, const uint32_t* b) {
    asm volatile(
        "mma.sync.aligned.m16n8k16.row.col.f32.f16.f16.f32 "
        "{%0,%1,%2,%3}, {%4,%5,%6,%7}, {%8,%9}, {%0,%1,%2,%3};"
        : "+f"(d[0]), "+f"(d[1]), "+f"(d[2]), "+f"(d[3])
        : "r"(a[0]), "r"(a[1]), "r"(a[2]), "r"(a[3]), "r"(b[0]), "r"(b[1]));
}
__device__ __forceinline__ void cp16(uint32_t dst, const void* src) {
    asm volatile("cp.async.ca.shared.global [%0], [%1], 16;" :: "r"(dst), "l"(src));
}
__device__ __forceinline__ void cp_commit() {
    asm volatile("cp.async.commit_group;" ::: "memory");
}
__device__ __forceinline__ void cp_wait0() {
    asm volatile("cp.async.wait_group 0;" ::: "memory");
}
// 8 fp32 -> 8 fp16 packed in one uint4
__device__ __forceinline__ void conv8h(const float4& a, const float4& b, uint4& h) {
    __half2 h0 = __floats2half2_rn(a.x, a.y);
    __half2 h1 = __floats2half2_rn(a.z, a.w);
    __half2 h2 = __floats2half2_rn(b.x, b.y);
    __half2 h3 = __floats2half2_rn(b.z, b.w);
    h = make_uint4(*reinterpret_cast<uint32_t*>(&h0), *reinterpret_cast<uint32_t*>(&h1),
                   *reinterpret_cast<uint32_t*>(&h2), *reinterpret_cast<uint32_t*>(&h3));
}

// ---------------- init / CSR build -----------------------------------------
__global__ void k_init() {
    int i = blockIdx.x * blockDim.x + threadIdx.x;
    int stride = gridDim.x * blockDim.x;
    for (int j = i; j < NN; j += stride) { g_deg[j] = 0; g_cnt[j] = 0; }
    if (i < OUT_DIM) { g_sum[i] = 0.f; g_sumsq[i] = 0.f; }
    if (i == 0) g_rowptr[0] = 0;
}

__global__ void k_count(const int* __restrict__ dst) {
    int i = blockIdx.x * blockDim.x + threadIdx.x;
    if (i < EE) atomicAdd(&g_deg[dst[i]], 1);
}

// merged transpose + fp16 round of all three weight matrices
__global__ void k_wtrans_all(const float* __restrict__ Ws,
                             const float* __restrict__ Wd,
                             const float* __restrict__ Wf)
{
    int i = blockIdx.x * blockDim.x + threadIdx.x;
    if (i < 65536) {
        int n = i >> 8, k = i & 255;
        g_wst[i] = __float2half_rn(Ws[k * HD + n]);
    } else if (i < 131072) {
        int j = i - 65536;
        int n = j >> 8, k = j & 255;
        g_wdt[j] = __float2half_rn(Wd[k * HD + n]);
    } else if (i < 147456) {
        int j = i - 131072;
        int n = j >> 8, k = j & 255;
        g_wft[j] = __float2half_rn(Wf[k * OUT_DIM + n]);
    }
}

// ---- multi-block scan ----
#define SCAN_B 196   // ceil(50000 / 256)
__global__ void k_scan1() {
    __shared__ int wsum[8];
    int tid = threadIdx.x, lane = tid & 31, wid = tid >> 5;
    int i = blockIdx.x * 256 + tid;
    int v = (i < NN) ? g_deg[i] : 0;
    int s = v;
#pragma unroll
    for (int off = 1; off < 32; off <<= 1) {
        int t = __shfl_up_sync(0xffffffffu, s, off);
        if (lane >= off) s += t;
    }
    if (lane == 31) wsum[wid] = s;
    __syncthreads();
    if (wid == 0 && lane < 8) {
        int w = wsum[lane];
#pragma unroll
        for (int off = 1; off < 8; off <<= 1) {
            int t = __shfl_up_sync(0xffu, w, off);
            if (lane >= off) w += t;
        }
        wsum[lane] = w;
    }
    __syncthreads();
    int incl = s + (wid ? wsum[wid - 1] : 0);
    if (i < NN) g_rowptr[i + 1] = incl;
    if (tid == 255) g_bsum[blockIdx.x] = incl;
}

__global__ void k_scan2() {
    __shared__ int wsum[8];
    int tid = threadIdx.x, lane = tid & 31, wid = tid >> 5;
    int v = (tid < SCAN_B) ? g_bsum[tid] : 0;
    int s = v;
#pragma unroll
    for (int off = 1; off < 32; off <<= 1) {
        int t = __shfl_up_sync(0xffffffffu, s, off);
        if (lane >= off) s += t;
    }
    if (lane == 31) wsum[wid] = s;
    __syncthreads();
    if (wid == 0 && lane < 8) {
        int w = wsum[lane];
#pragma unroll
        for (int off = 1; off < 8; off <<= 1) {
            int t = __shfl_up_sync(0xffu, w, off);
            if (lane >= off) w += t;
        }
        wsum[lane] = w;
    }
    __syncthreads();
    int incl = s + (wid ? wsum[wid - 1] : 0);
    g_boff[tid] = incl - v;
}

__global__ void k_scan3() {
    int i = blockIdx.x * 256 + threadIdx.x;
    if (i < NN) g_rowptr[i + 1] += g_boff[blockIdx.x];
}

__global__ void k_scatter(const int* __restrict__ src, const int* __restrict__ dst) {
    int i = blockIdx.x * blockDim.x + threadIdx.x;
    if (i < EE) {
        int v = dst[i];
        int pos = g_rowptr[v] + atomicAdd(&g_cnt[v], 1);
        g_ecol[pos] = src[i];
    }
}

// ---------------- pure fp16 GEMM: C[M,Nn] = A @ Bt^T + bias ----------------
// A fp32 row-major (K=256), rounded to fp16 in-kernel while staging.
// Bt pre-transposed fp16 ([n][k] K-major). Single product per fragment.
// CTA tile 128 x NT, 8 warps (4m x 2n), warp tile 32 x NT/2, m16n8k16.f16.
// HALF0: z==0 writes fp16 C. BNSTAT: fused BatchNorm column statistics.
template <int NT, bool HALF0, bool BNSTAT>
__global__ __launch_bounds__(256, 2)
void k_mma_gemm(
    const float* __restrict__ A,
    const __half* __restrict__ Bt0, const __half* __restrict__ Bt1,
    const float* __restrict__ bias0, const float* __restrict__ bias1,
    void* __restrict__ C0v, void* __restrict__ C1v,
    int M, int Nn)
{
    constexpr int A_BYTES = 128 * 80;            // 128 rows x (32 fp16 + pad)
    constexpr int B_BYTES = NT * 80;
    constexpr int STAGE   = A_BYTES + B_BYTES;
    constexpr int NG      = NT / 32;
    constexpr int B_IT    = NT * 4 / 256;

    extern __shared__ char smem[];
    const uint32_t sb = smem_u32(smem);
    const int tid  = threadIdx.x;
    const int lane = tid & 31;
    const int w    = tid >> 5;
    const int wr   = w & 3;
    const int wc   = w >> 2;

    const bool z0 = (blockIdx.z == 0);
    const __half* Bt   = z0 ? Bt0 : Bt1;
    const float*  bias = z0 ? bias0 : bias1;

    const int rowBase = blockIdx.y * 128;
    const int colBase = blockIdx.x * NT;

    float acc[2][2 * NG][4];
#pragma unroll
    for (int a = 0; a < 2; a++)
#pragma unroll
        for (int b = 0; b < 2 * NG; b++)
#pragma unroll
            for (int c = 0; c < 4; c++) acc[a][b][c] = 0.f;

    const int ar0 = tid >> 2, ap0 = tid & 3;
    const int ar1 = (tid + 256) >> 2, ap1 = ap0;
    int grow0 = rowBase + ar0; if (grow0 >= M) grow0 = M - 1;
    int grow1 = rowBase + ar1; if (grow1 >= M) grow1 = M - 1;

    float4 rA[4];

    auto loadA = [&](int ck) {
        const float* p0 = &A[(size_t)grow0 * 256 + ck * 32 + ap0 * 8];
        const float* p1 = &A[(size_t)grow1 * 256 + ck * 32 + ap1 * 8];
        rA[0] = *(const float4*)p0; rA[1] = *(const float4*)(p0 + 4);
        rA[2] = *(const float4*)p1; rA[3] = *(const float4*)(p1 + 4);
    };
    auto storeA = [&](int stage) {
        uint32_t st = (uint32_t)stage * STAGE;
        uint4 h;
        conv8h(rA[0], rA[1], h);
        *(uint4*)(smem + st + ar0 * 80 + ap0 * 16) = h;
        conv8h(rA[2], rA[3], h);
        *(uint4*)(smem + st + ar1 * 80 + ap1 * 16) = h;
    };
    auto loadB = [&](int ck, int stage) {
        uint32_t st = (uint32_t)stage * STAGE + A_BYTES;
#pragma unroll
        for (int i = 0; i < B_IT; i++) {
            int idx = tid + i * 256;
            int r = idx >> 2, p = idx & 3;
            uint32_t off = st + r * 80 + p * 16;
            size_t g = (size_t)(colBase + r) * 256 + ck * 32 + p * 8;
            cp16(sb + off, &Bt[g]);
        }
        cp_commit();
    };

    loadA(0);
    loadB(0, 0);
    storeA(0);
    cp_wait0();
    __syncthreads();

    const int lr = (lane & 7) + ((lane >> 3) & 1) * 8;
    const int lk = (lane >> 4) * 8;

    for (int ck = 0; ck < 8; ck++) {
        if (ck < 7) { loadA(ck + 1); loadB(ck + 1, (ck + 1) & 1); }

        const uint32_t stg = (uint32_t)(ck & 1) * STAGE;
        const uint32_t sA = sb + stg;
        const uint32_t sB = sA + A_BYTES;

#pragma unroll
        for (int k16 = 0; k16 < 32; k16 += 16) {
            uint32_t a[2][4];
#pragma unroll
            for (int mt = 0; mt < 2; mt++) {
                uint32_t off = (uint32_t)(wr * 32 + mt * 16 + lr) * 80 + (k16 + lk) * 2;
                ldm_x4(a[mt], sA + off);
            }
#pragma unroll
            for (int ng = 0; ng < NG; ng++) {
                uint32_t off = (uint32_t)(wc * (NT / 2) + ng * 16 + lr) * 80 + (k16 + lk) * 2;
                uint32_t t[4];
                ldm_x4(t, sB + off);
                uint32_t b0[2] = {t[0], t[2]}, b1[2] = {t[1], t[3]};
#pragma unroll
                for (int mt = 0; mt < 2; mt++) {
                    mma16816h(acc[mt][ng * 2],     a[mt], b0);
                    mma16816h(acc[mt][ng * 2 + 1], a[mt], b1);
                }
            }
        }

        if (ck < 7) { storeA((ck + 1) & 1); cp_wait0(); }
        __syncthreads();
    }

    // ---- epilogue (+ optional fused BatchNorm statistics) ----
    float colS[2 * NG][2], colQ[2 * NG][2];
    if (BNSTAT) {
#pragma unroll
        for (int nt = 0; nt < 2 * NG; nt++) {
            colS[nt][0] = colS[nt][1] = 0.f;
            colQ[nt][0] = colQ[nt][1] = 0.f;
        }
    }

#pragma unroll
    for (int mt = 0; mt < 2; mt++) {
#pragma unroll
        for (int nt = 0; nt < 2 * NG; nt++) {
            int gr = rowBase + wr * 32 + mt * 16 + (lane >> 2);
            int gc = colBase + wc * (NT / 2) + nt * 8 + (lane & 3) * 2;
            float b0 = bias[gc], b1 = bias[gc + 1];
            float v0 = acc[mt][nt][0] + b0, v1 = acc[mt][nt][1] + b1;
            float v2 = acc[mt][nt][2] + b0, v3 = acc[mt][nt][3] + b1;
            if (HALF0 && z0) {
                __half* Ch = (__half*)C0v;
                if (gr < M)
                    *(__half2*)&Ch[(size_t)gr * Nn + gc] = __floats2half2_rn(v0, v1);
                if (gr + 8 < M)
                    *(__half2*)&Ch[(size_t)(gr + 8) * Nn + gc] = __floats2half2_rn(v2, v3);
            } else {
                float* Cf = (float*)(z0 ? C0v : C1v);
                if (gr < M)
                    *(float2*)&Cf[(size_t)gr * Nn + gc] = make_float2(v0, v1);
                if (gr + 8 < M)
                    *(float2*)&Cf[(size_t)(gr + 8) * Nn + gc] = make_float2(v2, v3);
            }
            if (BNSTAT) {
                if (gr < M)     { colS[nt][0] += v0; colQ[nt][0] += v0 * v0;
                                  colS[nt][1] += v1; colQ[nt][1] += v1 * v1; }
                if (gr + 8 < M) { colS[nt][0] += v2; colQ[nt][0] += v2 * v2;
                                  colS[nt][1] += v3; colQ[nt][1] += v3 * v3; }
            }
        }
    }

    if (BNSTAT) {
#pragma unroll
        for (int nt = 0; nt < 2 * NG; nt++)
#pragma unroll
            for (int c = 0; c < 2; c++) {
#pragma unroll
                for (int msk = 4; msk <= 16; msk <<= 1) {
                    colS[nt][c] += __shfl_xor_sync(0xffffffffu, colS[nt][c], msk);
                    colQ[nt][c] += __shfl_xor_sync(0xffffffffu, colQ[nt][c], msk);
                }
            }
        __syncthreads();                   // mainloop SMEM fully retired
        float* bn = (float*)smem;          // [0:64) sum, [64:128) sumsq
        if (tid < 128) bn[tid] = 0.f;
        __syncthreads();
        if ((lane >> 2) == 0) {            // lanes 0..3 of each warp hold totals
#pragma unroll
            for (int nt = 0; nt < 2 * NG; nt++)
#pragma unroll
                for (int c = 0; c < 2; c++) {
                    int col = wc * (NT / 2) + nt * 8 + (lane & 3) * 2 + c;
                    atomicAdd(&bn[col], colS[nt][c]);
                    atomicAdd(&bn[64 + col], colQ[nt][c]);
                }
        }
        __syncthreads();
        if (tid < 64) {
            atomicAdd(&g_sum[tid],   bn[tid]);
            atomicAdd(&g_sumsq[tid], bn[64 + tid]);
        }
    }
}

// ---------------- edge aggregation: warp per dst node, online softmax ------
// R14 structure (proven fastest) with depth-2 data prefetch: at iteration j,
// issue the index load for j+3 and the data load for j+2, compute edge j.
// All indices clamped-valid; no predication, no shfl in the address chain.
__global__ __launch_bounds__(256) void k_edge_agg(
    const float* __restrict__ attn, const float* __restrict__ out_bias)
{
    int warp = (blockIdx.x * blockDim.x + threadIdx.x) >> 5;
    int lane = threadIdx.x & 31;
    if (warp >= NN) return;
    int v = warp;
    int base = lane * 8;

    float hd[8], at[8];
    {
        float4 d0 = *(const float4*)&g_hdst[v * HD + base];
        float4 d1 = *(const float4*)&g_hdst[v * HD + base + 4];
        hd[0]=d0.x; hd[1]=d0.y; hd[2]=d0.z; hd[3]=d0.w;
        hd[4]=d1.x; hd[5]=d1.y; hd[6]=d1.z; hd[7]=d1.w;
        float4 t0 = *(const float4*)&attn[base];
        float4 t1 = *(const float4*)&attn[base + 4];
        at[0]=t0.x; at[1]=t0.y; at[2]=t0.z; at[3]=t0.w;
        at[4]=t1.x; at[5]=t1.y; at[6]=t1.z; at[7]=t1.w;
    }

    float m = -CUDART_INF_F;
    float s = 0.f;
    float acc[8];
#pragma unroll
    for (int i = 0; i < 8; i++) acc[i] = 0.f;

    const int start = g_rowptr[v];
    const int end   = g_rowptr[v + 1];

    uint4 cur, nxt;
    int u2 = 0;
    if (start < end) {
        int u0 = g_ecol[start];
        cur = *(const uint4*)&g_hsrcH[(size_t)u0 * HD + base];
        int u1 = (start + 1 < end) ? g_ecol[start + 1] : u0;
        nxt = *(const uint4*)&g_hsrcH[(size_t)u1 * HD + base];
        u2 = (start + 2 < end) ? g_ecol[start + 2] : u1;
    }
    for (int j = start; j < end; j++) {
        int u3 = (j + 3 < end) ? g_ecol[j + 3] : u2;            // idx prefetch
        uint4 nn = *(const uint4*)&g_hsrcH[(size_t)u2 * HD + base];  // data j+2

        const __half2* ph = (const __half2*)&cur;
        float2 f0 = __half22float2(ph[0]);
        float2 f1 = __half22float2(ph[1]);
        float2 f2 = __half22float2(ph[2]);
        float2 f3 = __half22float2(ph[3]);
        float hs[8] = {f0.x, f0.y, f1.x, f1.y, f2.x, f2.y, f3.x, f3.y};

        float e = 0.f;
#pragma unroll
        for (int i = 0; i < 8; i++) {
            float x = hs[i] + hd[i];
            x = (x >= 0.f) ? x : SLOPE * x;
            e = fmaf(at[i], x, e);
        }
        e += __shfl_xor_sync(0xffffffffu, e, 1);
        e += __shfl_xor_sync(0xffffffffu, e, 2);
        e += __shfl_xor_sync(0xffffffffu, e, 4);
        float nm = fmaxf(m, e);
        float sc = __expf(m - nm);
        float p  = __expf(e - nm);
        s = s * sc + p;
#pragma unroll
        for (int i = 0; i < 8; i++)
            acc[i] = fmaf(acc[i], sc, p * hs[i]);
        m = nm;

        cur = nxt; nxt = nn; u2 = u3;
    }

    float inv = (s > 0.f) ? (1.0f / s) : 0.f;
    float4 ob0 = *(const float4*)&out_bias[base];
    float4 ob1 = *(const float4*)&out_bias[base + 4];
    float4 o0, o1;
    o0.x = acc[0] * inv + ob0.x; o0.y = acc[1] * inv + ob0.y;
    o0.z = acc[2] * inv + ob0.z; o0.w = acc[3] * inv + ob0.w;
    o1.x = acc[4] * inv + ob1.x; o1.y = acc[5] * inv + ob1.y;
    o1.z = acc[6] * inv + ob1.z; o1.w = acc[7] * inv + ob1.w;
    *(float4*)&g_hdst[v * HD + base]     = o0;   // rst (fc GEMM input)
    *(float4*)&g_hdst[v * HD + base + 4] = o1;
}

// ---------------- BatchNorm apply (finalize fused in, per-block) -----------
__global__ void k_bn_apply(const float* __restrict__ gamma,
                           const float* __restrict__ beta,
                           float* __restrict__ out)
{
    __shared__ float s_mu[OUT_DIM], s_istd[OUT_DIM];
    if (threadIdx.x < OUT_DIM) {
        int c = threadIdx.x;
        float mu = g_sum[c] / (float)NN;
        float var = g_sumsq[c] / (float)NN - mu * mu;
        s_mu[c] = mu;
        s_istd[c] = rsqrtf(var + BN_EPS);
    }
    __syncthreads();
    int i = blockIdx.x * blockDim.x + threadIdx.x;
    int stride = gridDim.x * blockDim.x;
    for (int j = i; j < NN * OUT_DIM; j += stride) {
        int c = j & 63;
        float x = (g_z[j] - s_mu[c]) * s_istd[c] * gamma[c] + beta[c];
        out[j] = (x >= 0.f) ? x : SLOPE * x;
    }
}

// ---------------- launch ----------------------------------------------------
extern "C" void kernel_launch(void* const* d_in, const int* in_sizes, int n_in,
                              void* d_out, int out_size)
{
    const float* feat    = (const float*)d_in[0];
    const int*   src     = (const int*)  d_in[1];
    const int*   dst     = (const int*)  d_in[2];
    const float* W_src   = (const float*)d_in[3];
    const float* b_src   = (const float*)d_in[4];
    const float* W_dst   = (const float*)d_in[5];
    const float* b_dst   = (const float*)d_in[6];
    const float* attn    = (const float*)d_in[7];
    const float* outbias = (const float*)d_in[8];
    const float* fc_W    = (const float*)d_in[9];
    const float* fc_b    = (const float*)d_in[10];
    const float* gamma   = (const float*)d_in[11];
    const float* beta    = (const float*)d_in[12];
    float* out = (float*)d_out;

    float *p_hdst, *p_z;
    __half* p_hsrcH;
    cudaGetSymbolAddress((void**)&p_hsrcH, g_hsrcH);
    cudaGetSymbolAddress((void**)&p_hdst, g_hdst);
    cudaGetSymbolAddress((void**)&p_z,    g_z);
    __half *p_wst, *p_wdt, *p_wft;
    cudaGetSymbolAddress((void**)&p_wst, g_wst);
    cudaGetSymbolAddress((void**)&p_wdt, g_wdt);
    cudaGetSymbolAddress((void**)&p_wft, g_wft);

    // stage = A + B, double-buffered
    const int SMEM_FRONT = 2 * (128 * 80 + 128 * 80);  // 40960
    const int SMEM_FC    = 2 * (128 * 80 + 64 * 80);   // 30720
    cudaFuncSetAttribute((const void*)k_mma_gemm<128, true, false>,
                         cudaFuncAttributeMaxDynamicSharedMemorySize, SMEM_FRONT);
    cudaFuncSetAttribute((const void*)k_mma_gemm<64, false, true>,
                         cudaFuncAttributeMaxDynamicSharedMemorySize, SMEM_FC);

    // Fork a side stream: CSR build (s0) overlaps weight prep + front GEMM (sB).
    cudaStream_t sB;
    cudaStreamCreateWithFlags(&sB, cudaStreamNonBlocking);
    cudaEvent_t evRoot, evB;
    cudaEventCreateWithFlags(&evRoot, cudaEventDisableTiming);
    cudaEventCreateWithFlags(&evB, cudaEventDisableTiming);

    cudaEventRecord(evRoot, 0);
    cudaStreamWaitEvent(sB, evRoot, 0);

    k_wtrans_all<<<(147456 + 255) / 256, 256, 0, sB>>>(W_src, W_dst, fc_W);  // 0
    k_init<<<256, 256>>>();                                                   // 1
    k_count<<<(EE + 255) / 256, 256>>>(dst);                                  // 2
    k_scan1<<<SCAN_B, 256>>>();                                               // 3
    k_scan2<<<1, 256>>>();                                                    // 4
    {                                                                         // 5: front GEMM
        dim3 grid(HD / 128, (NN + 127) / 128, 2);
        k_mma_gemm<128, true, false><<<grid, 256, SMEM_FRONT, sB>>>(
            feat, p_wst, p_wdt, b_src, b_dst,
            (void*)p_hsrcH, (void*)p_hdst, NN, HD);
    }
    cudaEventRecord(evB, sB);
    k_scan3<<<SCAN_B, 256>>>();                                               // 6
    k_scatter<<<(EE + 255) / 256, 256>>>(src, dst);                           // 7

    cudaStreamWaitEvent(0, evB, 0);

    k_edge_agg<<<(NN * 32 + 255) / 256, 256>>>(attn, outbias);                // 8

    {                                                                         // 9: fc GEMM + fused BN stats
        dim3 grid(1, (NN + 127) / 128, 1);
        k_mma_gemm<64, false, true><<<grid, 256, SMEM_FC>>>(
            p_hdst, p_wft, p_wft, fc_b, fc_b,
            (void*)p_z, (void*)p_z, NN, OUT_DIM);
    }

    k_bn_apply<<<512, 256>>>(gamma, beta, out);                               // 10
}